// round 2
// baseline (speedup 1.0000x reference)
#include <cuda_runtime.h>
#include <cuda_bf16.h>

// DifferentiableSMMPC: the reference iterates u <- u + (-inv(2R+eps) @ (2R u))
// starting from u == 0. Zero is a fixed point of that map, so u stays zero for
// all iterations and the returned slice u_traj[:, 0] is exactly a (B, D) block
// of zeros. The only required work is zero-filling d_out (poisoned to 0xAA by
// the harness). Everything else in the reference is dead code.

__global__ void smmpc_zero_fill_vec4(float4* __restrict__ out, int n_vec4) {
    int i = blockIdx.x * blockDim.x + threadIdx.x;
    if (i < n_vec4) {
        out[i] = make_float4(0.f, 0.f, 0.f, 0.f);
    }
}

__global__ void smmpc_zero_fill_tail(float* __restrict__ out, int start, int n) {
    int i = start + blockIdx.x * blockDim.x + threadIdx.x;
    if (i < n) {
        out[i] = 0.f;
    }
}

extern "C" void kernel_launch(void* const* d_in, const int* in_sizes, int n_in,
                              void* d_out, int out_size) {
    (void)d_in; (void)in_sizes; (void)n_in;

    float* out = (float*)d_out;
    int n_vec4 = out_size / 4;          // 262144 / 4 = 65536 float4 stores
    int tail_start = n_vec4 * 4;

    if (n_vec4 > 0) {
        const int threads = 256;
        int blocks = (n_vec4 + threads - 1) / threads;  // 256 blocks -> ~1 wave
        smmpc_zero_fill_vec4<<<blocks, threads>>>((float4*)out, n_vec4);
    }
    if (tail_start < out_size) {
        int tail_n = out_size - tail_start;
        const int threads = 128;
        int blocks = (tail_n + threads - 1) / threads;
        smmpc_zero_fill_tail<<<blocks, threads>>>(out, tail_start, out_size);
    }
}